// round 15
// baseline (speedup 1.0000x reference)
#include <cuda_runtime.h>
#include <math.h>

#define BZ   4
#define QL   512
#define CL   1536
#define KVL  2048
#define E    1024
#define NH   16
#define HD   64
#define MROWS (BZ*QL)   // 2048

#define OUT_K ((size_t)MROWS*E)                       // 2097152
#define OUT_V (OUT_K + (size_t)BZ*KVL*E)              // 10485760

#define PO_ROWS (BZ*NH*QL)    // 32768

// ---------------- scratch (tf32 stored as u32) -------------------------------
// k-pair permuted layout within each 8-group: perm8(t) = t<4 ? 2t : 2(t-4)+1.
// Applied to the k-dim of all mma operands (A-k and B-k identically permuted).
__device__ unsigned g_xt [MROWS*E];       // X  tf32, PERMUTED
__device__ unsigned g_wqt[E*E];           // Wq tf32 [n][k], PERMUTED
__device__ unsigned g_wkt[E*E];           // PERMUTED
__device__ unsigned g_wvt[E*E];           // PERMUTED
__device__ unsigned g_wot[E*E];           // PERMUTED
__device__ unsigned g_q  [MROWS*E];       // Q proj, tf32, 1/8-scaled, PERMUTED
__device__ unsigned g_ctx[MROWS*E];       // attention ctx, tf32, PERMUTED
__device__ unsigned g_kt [(size_t)BZ*KVL*E];  // full K tf32, PERMUTED
__device__ unsigned g_vt [(size_t)BZ*KVL*E];  // full V tf32, plain (staging)
__device__ unsigned g_vtT[(size_t)BZ*KVL*E];  // V transposed [b][h][d][pos-perm]

// split-KV partials
__device__ float g_po[(size_t)2*PO_ROWS*HD];  // unnormalized partial O
__device__ float g_pm[2*PO_ROWS];             // row max
__device__ float g_pl[2*PO_ROWS];             // row sum

// ---------------- helpers ----------------------------------------------------
__device__ __forceinline__ unsigned f2tf(float f) {
    unsigned u;
    asm("cvt.rna.tf32.f32 %0, %1;" : "=r"(u) : "f"(f));
    return u;
}

__device__ __forceinline__ void mma8(float* c,
                                     unsigned a0, unsigned a1, unsigned a2, unsigned a3,
                                     unsigned b0, unsigned b1)
{
    asm volatile(
        "mma.sync.aligned.m16n8k8.row.col.f32.tf32.tf32.f32 "
        "{%0,%1,%2,%3}, {%4,%5,%6,%7}, {%8,%9}, {%0,%1,%2,%3};\n"
        : "+f"(c[0]), "+f"(c[1]), "+f"(c[2]), "+f"(c[3])
        : "r"(a0), "r"(a1), "r"(a2), "r"(a3), "r"(b0), "r"(b1));
}

#define CP16(dst, src) \
    asm volatile("cp.async.cg.shared.global [%0], [%1], 16;\n" \
                 :: "r"(dst), "l"(src))
#define CPCOMMIT() asm volatile("cp.async.commit_group;\n" ::: "memory")
#define CPWAIT(n)  asm volatile("cp.async.wait_group %0;\n" :: "n"(n) : "memory")

// ---------------- convert inputs to tf32 (k-pair permuted) -------------------
__global__ void convert_tf32(const float4* __restrict__ X,
                             const float4* __restrict__ Wq,
                             const float4* __restrict__ Wk,
                             const float4* __restrict__ Wv,
                             const float4* __restrict__ Wo)
{
    int i = blockIdx.x*256 + threadIdx.x;
    const float4* src; unsigned* dst; int off4;
    if (i < 524288)       { src = X;  dst = g_xt;  off4 = i; }
    else if (i < 786432)  { src = Wq; dst = g_wqt; off4 = i - 524288; }
    else if (i < 1048576) { src = Wk; dst = g_wkt; off4 = i - 786432; }
    else if (i < 1310720) { src = Wv; dst = g_wvt; off4 = i - 1048576; }
    else                  { src = Wo; dst = g_wot; off4 = i - 1310720; }
    float4 v = src[off4];
    size_t eb = (size_t)off4*4;
    size_t G  = eb & ~(size_t)7;
    int   off = (eb & 4) ? 1 : 0;
    dst[G + off + 0] = f2tf(v.x);
    dst[G + off + 2] = f2tf(v.y);
    dst[G + off + 4] = f2tf(v.z);
    dst[G + off + 6] = f2tf(v.w);
}

// ---------------- cache copy: f32 to dout + tf32 to g_kt(perm)/g_vt ----------
__global__ void copy_cache(const float4* __restrict__ kc,
                           const float4* __restrict__ vc,
                           float* __restrict__ dout)
{
    const int per_b = CL*E/4;
    int idx = blockIdx.x*blockDim.x + threadIdx.x;
    if (idx >= BZ*per_b) return;
    int b = idx / per_b, rem = idx - b*per_b;
    size_t d = (size_t)b*(KVL*E/4) + rem;
    float4 k4 = kc[idx], v4 = vc[idx];
    ((float4*)(dout + OUT_K))[d] = k4;
    ((float4*)(dout + OUT_V))[d] = v4;
    {
        size_t eb = d*4;
        size_t G  = eb & ~(size_t)7;
        int   off = (eb & 4) ? 1 : 0;
        g_kt[G + off + 0] = f2tf(k4.x);
        g_kt[G + off + 2] = f2tf(k4.y);
        g_kt[G + off + 4] = f2tf(k4.z);
        g_kt[G + off + 6] = f2tf(k4.w);
    }
    uint4 u;
    u.x=f2tf(v4.x); u.y=f2tf(v4.y); u.z=f2tf(v4.z); u.w=f2tf(v4.w);
    ((uint4*)g_vt)[d] = u;
}

// ---------------- V transpose: g_vt[b][pos][h*64+d] -> g_vtT[b][h][d][permpos]
// 64x64 tiles; coalesced read, smem transpose, 16B permuted writes.
__global__ void vt_transpose()
{
    __shared__ unsigned s[64*65];
    int pt = blockIdx.x, h = blockIdx.y, b = blockIdx.z;
    int tid = threadIdx.x;
    const unsigned* src = g_vt + ((size_t)(b*KVL) + pt*64)*E + h*64;
    #pragma unroll
    for (int i = 0; i < 16; i++) {
        int idx = tid + i*256;
        int r = idx >> 6, c = idx & 63;
        s[r*65 + c] = src[(size_t)r*E + c];
    }
    __syncthreads();
    int d = tid >> 2, j = tid & 3;
    unsigned* dst = g_vtT + ((size_t)((b*NH + h)*64 + d))*KVL + pt*64;
    #pragma unroll
    for (int gi = 0; gi < 2; gi++) {
        int p8 = (2*j + gi)*8;
        uint4 u0, u1;
        u0.x = s[(p8+0)*65 + d]; u0.y = s[(p8+4)*65 + d];
        u0.z = s[(p8+1)*65 + d]; u0.w = s[(p8+5)*65 + d];
        u1.x = s[(p8+2)*65 + d]; u1.y = s[(p8+6)*65 + d];
        u1.z = s[(p8+3)*65 + d]; u1.w = s[(p8+7)*65 + d];
        *(uint4*)&dst[p8]     = u0;
        *(uint4*)&dst[p8 + 4] = u1;
    }
}

// ---------------- tf32 GEMM core (cp.async, 2-stage, LDS.64 fragments) -------
#define GST 24
#define GSTAGE (192*GST)      // (64 A-rows + 128 B-rows) * GST words

__device__ __forceinline__
void gemm_core(const unsigned* __restrict__ AGLOB,
               const unsigned* __restrict__ BGLOB,
               int bm, int nrow0, float acc[2][4][4])
{
    __shared__ __align__(16) unsigned sAB[2*GSTAGE];
    unsigned* Asm[2] = { sAB,          sAB + GSTAGE };
    unsigned* Bsm[2] = { sAB + 64*GST, sAB + GSTAGE + 64*GST };
    unsigned aAddr[2], bAddr[2];
    aAddr[0] = (unsigned)__cvta_generic_to_shared(Asm[0]);
    aAddr[1] = (unsigned)__cvta_generic_to_shared(Asm[1]);
    bAddr[0] = (unsigned)__cvta_generic_to_shared(Bsm[0]);
    bAddr[1] = (unsigned)__cvta_generic_to_shared(Bsm[1]);

    int tid = threadIdx.x;
    int warp = tid >> 5, lane = tid & 31, g = lane >> 2, tig = lane & 3;
    int wm = (warp >> 2)*32, wn = (warp & 3)*32;
    int r0c = tid >> 2, c0c = (tid & 3)*4;
    int r1c = r0c + 64;

    auto issue = [&](int st, int k0) {
        CP16(aAddr[st] + (unsigned)((r0c*GST + c0c)*4),
             AGLOB + (size_t)(bm + r0c)*E + k0 + c0c);
        CP16(bAddr[st] + (unsigned)((r0c*GST + c0c)*4),
             BGLOB + (size_t)(nrow0 + r0c)*E + k0 + c0c);
        CP16(bAddr[st] + (unsigned)((r1c*GST + c0c)*4),
             BGLOB + (size_t)(nrow0 + r1c)*E + k0 + c0c);
    };

    #pragma unroll
    for (int mt = 0; mt < 2; mt++)
        #pragma unroll
        for (int nt = 0; nt < 4; nt++)
            #pragma unroll
            for (int i = 0; i < 4; i++) acc[mt][nt][i] = 0.f;

    issue(0, 0);  CPCOMMIT();
    issue(1, 16); CPCOMMIT();

    for (int kt = 0; kt < 64; kt++) {
        int cur = kt & 1;
        if (kt < 63) { CPWAIT(1); } else { CPWAIT(0); }
        __syncthreads();
        #pragma unroll
        for (int kh = 0; kh < 2; kh++) {
            int kb = kh*8 + 2*tig;   // permuted pair base
            uint2 af[2][2];
            #pragma unroll
            for (int mt = 0; mt < 2; mt++) {
                int r = wm + mt*16;
                af[mt][0] = *(const uint2*)&Asm[cur][(r+g  )*GST + kb];
                af[mt][1] = *(const uint2*)&Asm[cur][(r+g+8)*GST + kb];
            }
            uint2 bf[4];
            #pragma unroll
            for (int nt = 0; nt < 4; nt++) {
                int cidx = wn + nt*8 + g;
                bf[nt] = *(const uint2*)&Bsm[cur][cidx*GST + kb];
            }
            #pragma unroll
            for (int mt = 0; mt < 2; mt++)
                #pragma unroll
                for (int nt = 0; nt < 4; nt++)
                    mma8(acc[mt][nt], af[mt][0].x, af[mt][1].x,
                         af[mt][0].y, af[mt][1].y, bf[nt].x, bf[nt].y);
        }
        __syncthreads();
        if (kt + 2 < 64) { issue(cur, (kt+2)*16); CPCOMMIT(); }
    }
}

// ---------------- QKV projection ---------------------------------------------
__global__ __launch_bounds__(256, 3)
void gemm_qkv(const float* __restrict__ bq, const float* __restrict__ bk,
              const float* __restrict__ bv, float* __restrict__ dout)
{
    int bn = blockIdx.x*128, bm = blockIdx.y*64;
    int seg = bn >> 10;            // 0=Q 1=K 2=V
    int nrow0 = bn & (E-1);
    const unsigned* Bglob = (seg == 0) ? g_wqt : (seg == 1) ? g_wkt : g_wvt;
    const float*    bias  = (seg == 0) ? bq   : (seg == 1) ? bk    : bv;

    float acc[2][4][4];
    gemm_core(g_xt, Bglob, bm, nrow0, acc);

    int tid = threadIdx.x;
    int warp = tid >> 5, lane = tid & 31, g = lane >> 2, tig = lane & 3;
    int wm = (warp >> 2)*32, wn = (warp & 3)*32;

    int p0 = (tig < 2) ? (4*tig) : (4*(tig-2) + 1);

    #pragma unroll
    for (int mt = 0; mt < 2; mt++) {
        int m = bm + wm + mt*16 + g;
        #pragma unroll
        for (int nt = 0; nt < 4; nt++) {
            int nl = nrow0 + wn + nt*8 + 2*tig;
            float b0 = bias[nl], b1 = bias[nl+1];
            float v0 = acc[mt][nt][0] + b0, v1 = acc[mt][nt][1] + b1;
            float v2 = acc[mt][nt][2] + b0, v3 = acc[mt][nt][3] + b1;
            int base8 = nl & ~7;
            if (seg == 0) {
                size_t r0 = (size_t)m*E + base8;
                size_t r1 = (size_t)(m+8)*E + base8;
                g_q[r0 + p0]     = f2tf(v0*0.125f);
                g_q[r0 + p0 + 2] = f2tf(v1*0.125f);
                g_q[r1 + p0]     = f2tf(v2*0.125f);
                g_q[r1 + p0 + 2] = f2tf(v3*0.125f);
            } else {
                float* fbase = dout + (seg == 1 ? OUT_K : OUT_V);
                int ba = m >> 9,      t0 = m & 511;
                int bb = (m+8) >> 9,  t1 = (m+8) & 511;
                size_t ra = ((size_t)(ba*KVL) + CL + t0)*E;
                size_t rb = ((size_t)(bb*KVL) + CL + t1)*E;
                *(float2*)&fbase[ra + nl] = make_float2(v0, v1);
                *(float2*)&fbase[rb + nl] = make_float2(v2, v3);
                if (seg == 1) {
                    g_kt[ra + base8 + p0]     = f2tf(v0);
                    g_kt[ra + base8 + p0 + 2] = f2tf(v1);
                    g_kt[rb + base8 + p0]     = f2tf(v2);
                    g_kt[rb + base8 + p0 + 2] = f2tf(v3);
                } else {
                    uint2 u0; u0.x = f2tf(v0); u0.y = f2tf(v1);
                    uint2 u1; u1.x = f2tf(v2); u1.y = f2tf(v3);
                    *(uint2*)&g_vt[ra + nl] = u0;
                    *(uint2*)&g_vt[rb + nl] = u1;
                }
            }
        }
    }
}

// ---------------- output projection ------------------------------------------
__global__ __launch_bounds__(256, 3)
void gemm_out(const float* __restrict__ bo, float* __restrict__ dout)
{
    int bn = blockIdx.x*128, bm = blockIdx.y*64;

    float acc[2][4][4];
    gemm_core(g_ctx, g_wot, bm, bn, acc);

    int tid = threadIdx.x;
    int warp = tid >> 5, lane = tid & 31, g = lane >> 2, tig = lane & 3;
    int wm = (warp >> 2)*32, wn = (warp & 3)*32;

    #pragma unroll
    for (int mt = 0; mt < 2; mt++) {
        int m = bm + wm + mt*16 + g;
        #pragma unroll
        for (int nt = 0; nt < 4; nt++) {
            int n = bn + wn + nt*8 + 2*tig;
            float b0 = bo[n], b1 = bo[n+1];
            *(float2*)&dout[(size_t)m*E + n] =
                make_float2(acc[mt][nt][0] + b0, acc[mt][nt][1] + b1);
            *(float2*)&dout[(size_t)(m+8)*E + n] =
                make_float2(acc[mt][nt][2] + b0, acc[mt][nt][3] + b1);
        }
    }
}

// ---------------- flash attention: split-KV, LDS.64 S and PV paths -----------
#define SWKN(r,o) ((o) ^ ((((unsigned)(r))&3u)<<3))

__global__ __launch_bounds__(128, 4)
void attn(const float* __restrict__ amask)
{
    __shared__ __align__(16) unsigned sQ[64*64];
    __shared__ __align__(16) unsigned sK[64*64];
    __shared__ __align__(16) unsigned sVT[64*64];   // [d][pos-perm], swizzled

    int qt    = blockIdx.x >> 1;
    int chunk = blockIdx.x & 1;
    int h = blockIdx.y, b = blockIdx.z;

    int tid  = threadIdx.x;
    int warp = tid >> 5, lane = tid & 31, g = lane >> 2, tig = lane & 3;
    int m0 = warp*16;

    int nkt  = 25 + qt;
    int half = nkt >> 1;
    int t0   = chunk ? half : 0;
    int ntiles = chunk ? (nkt - half) : half;

    unsigned qAddr = (unsigned)__cvta_generic_to_shared(sQ);
    unsigned kAddr = (unsigned)__cvta_generic_to_shared(sK);
    unsigned vAddr = (unsigned)__cvta_generic_to_shared(sVT);

    const unsigned* kg = g_kt  + ((size_t)b*KVL)*E + h*HD;
    const unsigned* vg = g_vtT + ((size_t)(b*NH + h))*HD*KVL;

    auto issueK = [&](int tile) {
        const unsigned* src = kg + (size_t)tile*64*E;
        #pragma unroll
        for (int i = 0; i < 8; i++) {
            int c = tid + i*128;
            int row = c >> 4, c4 = (c & 15)*4;
            CP16(kAddr + (unsigned)((row*64 + SWKN(row, c4))*4),
                 src + (size_t)row*E + c4);
        }
    };
    auto issueV = [&](int tile) {
        #pragma unroll
        for (int i = 0; i < 8; i++) {
            int c = tid + i*128;
            int d = c >> 4, c4 = (c & 15)*4;
            CP16(vAddr + (unsigned)((d*64 + (c4 ^ ((d&3)<<3)))*4),
                 vg + (size_t)d*KVL + tile*64 + c4);
        }
    };

    // prologue: Q tile + first K,V — one commit group
    {
        const unsigned* src = g_q + ((size_t)(b*QL + qt*64))*E + h*HD;
        #pragma unroll
        for (int i = 0; i < 8; i++) {
            int c = tid + i*128;
            int row = c >> 4, c4 = (c & 15)*4;
            CP16(qAddr + (unsigned)((row*64 + SWKN(row, c4))*4),
                 src + (size_t)row*E + c4);
        }
    }
    issueK(t0);
    issueV(t0);
    CPCOMMIT();

    float O[8][4];
    #pragma unroll
    for (int nt = 0; nt < 8; nt++)
        #pragma unroll
        for (int i = 0; i < 4; i++) O[nt][i] = 0.f;
    float mi0 = -1e30f, mi1 = -1e30f, li0 = 0.f, li1 = 0.f;

    for (int it = 0; it < ntiles; it++) {
        int kt = t0 + it;
        CPWAIT(0);
        __syncthreads();

        // ---- S = (Q/8) K^T  (LDS.64 paired fragments) ----
        float s[8][4];
        #pragma unroll
        for (int nt = 0; nt < 8; nt++)
            #pragma unroll
            for (int i = 0; i < 4; i++) s[nt][i] = 0.f;
        #pragma unroll
        for (int kc = 0; kc < 8; kc++) {
            int kb = kc*8 + 2*tig;
            uint2 aLo = *(const uint2*)&sQ[(m0+g  )*64 + SWKN(m0+g,   kb)];
            uint2 aHi = *(const uint2*)&sQ[(m0+g+8)*64 + SWKN(m0+g+8, kb)];
            #pragma unroll
            for (int nt = 0; nt < 8; nt++) {
                int col = nt*8 + g;
                uint2 bp = *(const uint2*)&sK[col*64 + SWKN(col, kb)];
                mma8(s[nt], aLo.x, aHi.x, aLo.y, aHi.y, bp.x, bp.y);
            }
        }

        __syncthreads();                         // sK fully consumed
        if (it + 1 < ntiles) issueK(kt+1);

        // ---- mask + online softmax ----
        int c0 = kt*64;
        const float* am = amask + (size_t)b*(CL+QL) + c0;
        bool causal = (chunk == 1) && (it == ntiles-1);
        #pragma unroll
        for (int nt = 0; nt < 8; nt++) {
            int j0 = nt*8 + 2*tig, j1 = j0 + 1;
            float a0 = __ldg(am + j0), a1 = __ldg(am + j1);
            s[nt][0] += a0; s[nt][1] += a1; s[nt][2] += a0; s[nt][3] += a1;
            if (causal) {
                int r0 = CL + qt*64 + m0 + g, r1 = r0 + 8;
                int cj0 = c0 + j0, cj1 = c0 + j1;
                if (cj0 > r0) s[nt][0] = -1e30f;
                if (cj1 > r0) s[nt][1] = -1e30f;
                if (cj0 > r1) s[nt][2] = -1e30f;
                if (cj1 > r1) s[nt][3] = -1e30f;
            }
        }

        float mx0 = -1e30f, mx1 = -1e30f;
        #pragma unroll
        for (int nt = 0; nt < 8; nt++) {
            mx0 = fmaxf(mx0, fmaxf(s[nt][0], s[nt][1]));
            mx1 = fmaxf(mx1, fmaxf(s[nt][2], s[nt][3]));
        }
        mx0 = fmaxf(mx0, __shfl_xor_sync(0xffffffffu, mx0, 1));
        mx0 = fmaxf(mx0, __shfl_xor_sync(0xffffffffu, mx0, 2));
        mx1 = fmaxf(mx1, __shfl_xor_sync(0xffffffffu, mx1, 1));
        mx1 = fmaxf(mx1, __shfl_xor_sync(0xffffffffu, mx1, 2));

        float mn0 = fmaxf(mi0, mx0), mn1 = fmaxf(mi1, mx1);
        float cor0 = __expf(mi0 - mn0), cor1 = __expf(mi1 - mn1);
        mi0 = mn0; mi1 = mn1;

        float sum0 = 0.f, sum1 = 0.f;
        #pragma unroll
        for (int nt = 0; nt < 8; nt++) {
            s[nt][0] = __expf(s[nt][0] - mn0); sum0 += s[nt][0];
            s[nt][1] = __expf(s[nt][1] - mn0); sum0 += s[nt][1];
            s[nt][2] = __expf(s[nt][2] - mn1); sum1 += s[nt][2];
            s[nt][3] = __expf(s[nt][3] - mn1); sum1 += s[nt][3];
        }
        sum0 += __shfl_xor_sync(0xffffffffu, sum0, 1);
        sum0 += __shfl_xor_sync(0xffffffffu, sum0, 2);
        sum1 += __shfl_xor_sync(0xffffffffu, sum1, 1);
        sum1 += __shfl_xor_sync(0xffffffffu, sum1, 2);
        li0 = li0*cor0 + sum0;
        li1 = li1*cor1 + sum1;
        #pragma unroll
        for (int nt = 0; nt < 8; nt++) {
            O[nt][0] *= cor0; O[nt][1] *= cor0;
            O[nt][2] *= cor1; O[nt][3] *= cor1;
        }

        // ---- O += P V  (P via shfl; V fragments now LDS.64 from sVT) ----
        int l1 = (lane & 28) + (tig >> 1);
        int l2 = l1 + 2;
        bool odd = (tig & 1);
        #pragma unroll
        for (int kc = 0; kc < 8; kc++) {
            unsigned u0 = f2tf(s[kc][0]), u1 = f2tf(s[kc][1]);
            unsigned u2 = f2tf(s[kc][2]), u3 = f2tf(s[kc][3]);
            unsigned s00 = __shfl_sync(0xffffffffu, u0, l1);
            unsigned s01 = __shfl_sync(0xffffffffu, u1, l1);
            unsigned s02 = __shfl_sync(0xffffffffu, u2, l1);
            unsigned s03 = __shfl_sync(0xffffffffu, u3, l1);
            unsigned s10 = __shfl_sync(0xffffffffu, u0, l2);
            unsigned s11 = __shfl_sync(0xffffffffu, u1, l2);
            unsigned s12 = __shfl_sync(0xffffffffu, u2, l2);
            unsigned s13 = __shfl_sync(0xffffffffu, u3, l2);
            unsigned a0 = odd ? s01 : s00;
            unsigned a1 = odd ? s03 : s02;
            unsigned a2 = odd ? s11 : s10;
            unsigned a3 = odd ? s13 : s12;
            int kb2 = kc*8 + 2*tig;
            #pragma unroll
            for (int nt = 0; nt < 8; nt++) {
                int dcol = nt*8 + g;
                uint2 bp = *(const uint2*)&sVT[dcol*64 + (kb2 ^ ((dcol&3)<<3))];
                mma8(O[nt], a0, a1, a2, a3, bp.x, bp.y);
            }
        }

        __syncthreads();                          // sVT fully consumed
        if (it + 1 < ntiles) issueV(kt+1);
        CPCOMMIT();                               // group = K(t+1)+V(t+1)
    }

    // ---- write partials (unnormalized O, m, l) ----
    size_t rowbase = ((size_t)(b*NH + h))*QL + qt*64;
    float* po = g_po + ((size_t)chunk*PO_ROWS + rowbase)*HD;
    #pragma unroll
    for (int nt = 0; nt < 8; nt++) {
        int col = nt*8 + 2*tig;
        *(float2*)&po[(size_t)(m0+g)*HD + col]   = make_float2(O[nt][0], O[nt][1]);
        *(float2*)&po[(size_t)(m0+g+8)*HD + col] = make_float2(O[nt][2], O[nt][3]);
    }
    if (tig == 0) {
        size_t mb = (size_t)chunk*PO_ROWS + rowbase;
        g_pm[mb + m0 + g]     = mi0;
        g_pl[mb + m0 + g]     = li0;
        g_pm[mb + m0 + g + 8] = mi1;
        g_pl[mb + m0 + g + 8] = li1;
    }
}

// ---------------- combine split-KV partials -> ctx (tf32, PERMUTED) ----------
__global__ void combine_attn()
{
    int idx = blockIdx.x*256 + threadIdx.x;      // 0 .. 524287
    int d4  = idx & 15;
    int row = idx >> 4;                          // 0 .. 32767

    float m0 = g_pm[row], m1 = g_pm[PO_ROWS + row];
    float l0 = g_pl[row], l1 = g_pl[PO_ROWS + row];
    float m  = fmaxf(m0, m1);
    float w0 = __expf(m0 - m), w1 = __expf(m1 - m);
    float inv = 1.f / (w0*l0 + w1*l1);
    w0 *= inv; w1 *= inv;

    float4 o0 = ((const float4*)g_po)[(size_t)row*16 + d4];
    float4 o1 = ((const float4*)g_po)[(size_t)(PO_ROWS + row)*16 + d4];

    int q = row & 511, h = (row >> 9) & 15, b = row >> 13;
    size_t base = (size_t)(b*QL + q)*E + h*HD + d4*4;
    size_t G    = base & ~(size_t)7;
    int   off   = (base & 4) ? 1 : 0;
    g_ctx[G + off + 0] = f2tf(w0*o0.x + w1*o1.x);
    g_ctx[G + off + 2] = f2tf(w0*o0.y + w1*o1.y);
    g_ctx[G + off + 4] = f2tf(w0*o0.z + w1*o1.z);
    g_ctx[G + off + 6] = f2tf(w0*o0.w + w1*o1.w);
}

// ---------------- launch ----------------------------------------------------
extern "C" void kernel_launch(void* const* d_in, const int* in_sizes, int n_in,
                              void* d_out, int out_size)
{
    const float* X     = (const float*)d_in[0];
    const float* amask = (const float*)d_in[1];
    const float* kc    = (const float*)d_in[2];
    const float* vc    = (const float*)d_in[3];
    const float* Wq    = (const float*)d_in[4];
    const float* bq    = (const float*)d_in[5];
    const float* Wk    = (const float*)d_in[6];
    const float* bk    = (const float*)d_in[7];
    const float* Wv    = (const float*)d_in[8];
    const float* bv    = (const float*)d_in[9];
    const float* Wo    = (const float*)d_in[10];
    const float* bo    = (const float*)d_in[11];
    float* out = (float*)d_out;

    convert_tf32<<<6144, 256>>>((const float4*)X, (const float4*)Wq,
                                (const float4*)Wk, (const float4*)Wv,
                                (const float4*)Wo);
    {
        int total = BZ*CL*E/4;
        copy_cache<<<(total + 255)/256, 256>>>((const float4*)kc,
                                               (const float4*)vc, out);
    }
    {
        dim3 grid(3*E/128, MROWS/64);        // 24 x 32 = 768 blocks
        gemm_qkv<<<grid, 256>>>(bq, bk, bv, out);
    }
    {
        dim3 grid(KVL/64, NH, BZ);           // 32 x 16 x 4
        vt_transpose<<<grid, 256>>>();
    }
    {
        dim3 grid(16, NH, BZ);               // (qt,chunk) x 16 x 4 = 1024 blocks
        attn<<<grid, 128>>>(amask);
    }
    combine_attn<<<2048, 256>>>();
    {
        dim3 grid(E/128, MROWS/64);          // 8 x 32 = 256 blocks
        gemm_out<<<grid, 256>>>(bo, out);
    }
}

// round 16
// speedup vs baseline: 1.0911x; 1.0911x over previous
#include <cuda_runtime.h>
#include <math.h>

#define BZ   4
#define QL   512
#define CL   1536
#define KVL  2048
#define E    1024
#define NH   16
#define HD   64
#define MROWS (BZ*QL)   // 2048

#define OUT_K ((size_t)MROWS*E)                       // 2097152
#define OUT_V (OUT_K + (size_t)BZ*KVL*E)              // 10485760

#define PO_ROWS (BZ*NH*QL)    // 32768

// ---------------- scratch (tf32 stored as u32) -------------------------------
// k-pair permuted layout within each 8-group: perm8(t) = t<4 ? 2t : 2(t-4)+1.
__device__ unsigned g_xt [MROWS*E];       // X  tf32, PERMUTED
__device__ unsigned g_wqt[E*E];           // Wq tf32 [n][k], PERMUTED
__device__ unsigned g_wkt[E*E];           // PERMUTED
__device__ unsigned g_wvt[E*E];           // PERMUTED
__device__ unsigned g_wot[E*E];           // PERMUTED
__device__ unsigned g_q  [MROWS*E];       // Q proj, tf32, 1/8-scaled, PERMUTED
__device__ unsigned g_ctx[MROWS*E];       // attention ctx, tf32, PERMUTED
__device__ unsigned g_kt [(size_t)BZ*KVL*E];  // full K tf32, PERMUTED
__device__ unsigned g_vt [(size_t)BZ*KVL*E];  // full V tf32, plain layout

// split-KV partials
__device__ float g_po[(size_t)2*PO_ROWS*HD];  // unnormalized partial O
__device__ float g_pm[2*PO_ROWS];             // row max
__device__ float g_pl[2*PO_ROWS];             // row sum

// ---------------- helpers ----------------------------------------------------
__device__ __forceinline__ unsigned f2tf(float f) {
    unsigned u;
    asm("cvt.rna.tf32.f32 %0, %1;" : "=r"(u) : "f"(f));
    return u;
}

__device__ __forceinline__ void mma8(float* c,
                                     unsigned a0, unsigned a1, unsigned a2, unsigned a3,
                                     unsigned b0, unsigned b1)
{
    asm volatile(
        "mma.sync.aligned.m16n8k8.row.col.f32.tf32.tf32.f32 "
        "{%0,%1,%2,%3}, {%4,%5,%6,%7}, {%8,%9}, {%0,%1,%2,%3};\n"
        : "+f"(c[0]), "+f"(c[1]), "+f"(c[2]), "+f"(c[3])
        : "r"(a0), "r"(a1), "r"(a2), "r"(a3), "r"(b0), "r"(b1));
}

#define CP16(dst, src) \
    asm volatile("cp.async.cg.shared.global [%0], [%1], 16;\n" \
                 :: "r"(dst), "l"(src))
#define CPCOMMIT() asm volatile("cp.async.commit_group;\n" ::: "memory")
#define CPWAIT(n)  asm volatile("cp.async.wait_group %0;\n" :: "n"(n) : "memory")

// ---------------- convert inputs to tf32 (k-pair permuted) -------------------
__global__ void convert_tf32(const float4* __restrict__ X,
                             const float4* __restrict__ Wq,
                             const float4* __restrict__ Wk,
                             const float4* __restrict__ Wv,
                             const float4* __restrict__ Wo)
{
    int i = blockIdx.x*256 + threadIdx.x;
    const float4* src; unsigned* dst; int off4;
    if (i < 524288)       { src = X;  dst = g_xt;  off4 = i; }
    else if (i < 786432)  { src = Wq; dst = g_wqt; off4 = i - 524288; }
    else if (i < 1048576) { src = Wk; dst = g_wkt; off4 = i - 786432; }
    else if (i < 1310720) { src = Wv; dst = g_wvt; off4 = i - 1048576; }
    else                  { src = Wo; dst = g_wot; off4 = i - 1310720; }
    float4 v = src[off4];
    size_t eb = (size_t)off4*4;
    size_t G  = eb & ~(size_t)7;
    int   off = (eb & 4) ? 1 : 0;
    dst[G + off + 0] = f2tf(v.x);
    dst[G + off + 2] = f2tf(v.y);
    dst[G + off + 4] = f2tf(v.z);
    dst[G + off + 6] = f2tf(v.w);
}

// ---------------- cache copy: f32 to dout + tf32 to g_kt(perm)/g_vt ----------
__global__ void copy_cache(const float4* __restrict__ kc,
                           const float4* __restrict__ vc,
                           float* __restrict__ dout)
{
    const int per_b = CL*E/4;
    int idx = blockIdx.x*blockDim.x + threadIdx.x;
    if (idx >= BZ*per_b) return;
    int b = idx / per_b, rem = idx - b*per_b;
    size_t d = (size_t)b*(KVL*E/4) + rem;
    float4 k4 = kc[idx], v4 = vc[idx];
    ((float4*)(dout + OUT_K))[d] = k4;
    ((float4*)(dout + OUT_V))[d] = v4;
    {
        size_t eb = d*4;
        size_t G  = eb & ~(size_t)7;
        int   off = (eb & 4) ? 1 : 0;
        g_kt[G + off + 0] = f2tf(k4.x);
        g_kt[G + off + 2] = f2tf(k4.y);
        g_kt[G + off + 4] = f2tf(k4.z);
        g_kt[G + off + 6] = f2tf(k4.w);
    }
    uint4 u;
    u.x=f2tf(v4.x); u.y=f2tf(v4.y); u.z=f2tf(v4.z); u.w=f2tf(v4.w);
    ((uint4*)g_vt)[d] = u;
}

// ---------------- tf32 GEMM core (cp.async, 2-stage, BK=32, LDS.64) ----------
// BM=64, BN=128, BK=32, 256 thr, warp grid 2x4, warp tile 32x32, stride 40.
// Half the k-iterations (32) and barriers vs BK=16; k-order preserved exactly.
#define GST 40
#define GSTAGE (192*GST)      // (64 A-rows + 128 B-rows) * GST words

__device__ __forceinline__
void gemm_core(const unsigned* __restrict__ AGLOB,
               const unsigned* __restrict__ BGLOB,
               int bm, int nrow0, float acc[2][4][4])
{
    __shared__ __align__(16) unsigned sAB[2*GSTAGE];
    unsigned* Asm[2] = { sAB,          sAB + GSTAGE };
    unsigned* Bsm[2] = { sAB + 64*GST, sAB + GSTAGE + 64*GST };
    unsigned aAddr[2], bAddr[2];
    aAddr[0] = (unsigned)__cvta_generic_to_shared(Asm[0]);
    aAddr[1] = (unsigned)__cvta_generic_to_shared(Asm[1]);
    bAddr[0] = (unsigned)__cvta_generic_to_shared(Bsm[0]);
    bAddr[1] = (unsigned)__cvta_generic_to_shared(Bsm[1]);

    int tid = threadIdx.x;
    int warp = tid >> 5, lane = tid & 31, g = lane >> 2, tig = lane & 3;
    int wm = (warp >> 2)*32, wn = (warp & 3)*32;
    int rc  = tid >> 3;            // 0..31
    int cc  = (tid & 7)*4;         // 0..28

    auto issue = [&](int st, int k0) {
        CP16(aAddr[st] + (unsigned)((rc*GST + cc)*4),
             AGLOB + (size_t)(bm + rc)*E + k0 + cc);
        CP16(aAddr[st] + (unsigned)(((rc+32)*GST + cc)*4),
             AGLOB + (size_t)(bm + rc + 32)*E + k0 + cc);
        #pragma unroll
        for (int br = 0; br < 4; br++)
            CP16(bAddr[st] + (unsigned)(((rc + br*32)*GST + cc)*4),
                 BGLOB + (size_t)(nrow0 + rc + br*32)*E + k0 + cc);
    };

    #pragma unroll
    for (int mt = 0; mt < 2; mt++)
        #pragma unroll
        for (int nt = 0; nt < 4; nt++)
            #pragma unroll
            for (int i = 0; i < 4; i++) acc[mt][nt][i] = 0.f;

    issue(0, 0);  CPCOMMIT();
    issue(1, 32); CPCOMMIT();

    for (int kt = 0; kt < 32; kt++) {
        int cur = kt & 1;
        if (kt < 31) { CPWAIT(1); } else { CPWAIT(0); }
        __syncthreads();
        #pragma unroll
        for (int kh = 0; kh < 4; kh++) {
            int kb = kh*8 + 2*tig;   // permuted pair base
            uint2 af[2][2];
            #pragma unroll
            for (int mt = 0; mt < 2; mt++) {
                int r = wm + mt*16;
                af[mt][0] = *(const uint2*)&Asm[cur][(r+g  )*GST + kb];
                af[mt][1] = *(const uint2*)&Asm[cur][(r+g+8)*GST + kb];
            }
            uint2 bf[4];
            #pragma unroll
            for (int nt = 0; nt < 4; nt++) {
                int cidx = wn + nt*8 + g;
                bf[nt] = *(const uint2*)&Bsm[cur][cidx*GST + kb];
            }
            #pragma unroll
            for (int mt = 0; mt < 2; mt++)
                #pragma unroll
                for (int nt = 0; nt < 4; nt++)
                    mma8(acc[mt][nt], af[mt][0].x, af[mt][1].x,
                         af[mt][0].y, af[mt][1].y, bf[nt].x, bf[nt].y);
        }
        __syncthreads();
        if (kt + 2 < 32) { issue(cur, (kt+2)*32); CPCOMMIT(); }
    }
}

// ---------------- QKV projection ---------------------------------------------
__global__ __launch_bounds__(256)
void gemm_qkv(const float* __restrict__ bq, const float* __restrict__ bk,
              const float* __restrict__ bv, float* __restrict__ dout)
{
    int bn = blockIdx.x*128, bm = blockIdx.y*64;
    int seg = bn >> 10;            // 0=Q 1=K 2=V
    int nrow0 = bn & (E-1);
    const unsigned* Bglob = (seg == 0) ? g_wqt : (seg == 1) ? g_wkt : g_wvt;
    const float*    bias  = (seg == 0) ? bq   : (seg == 1) ? bk    : bv;

    float acc[2][4][4];
    gemm_core(g_xt, Bglob, bm, nrow0, acc);

    int tid = threadIdx.x;
    int warp = tid >> 5, lane = tid & 31, g = lane >> 2, tig = lane & 3;
    int wm = (warp >> 2)*32, wn = (warp & 3)*32;

    int p0 = (tig < 2) ? (4*tig) : (4*(tig-2) + 1);

    #pragma unroll
    for (int mt = 0; mt < 2; mt++) {
        int m = bm + wm + mt*16 + g;
        #pragma unroll
        for (int nt = 0; nt < 4; nt++) {
            int nl = nrow0 + wn + nt*8 + 2*tig;
            float b0 = bias[nl], b1 = bias[nl+1];
            float v0 = acc[mt][nt][0] + b0, v1 = acc[mt][nt][1] + b1;
            float v2 = acc[mt][nt][2] + b0, v3 = acc[mt][nt][3] + b1;
            int base8 = nl & ~7;
            if (seg == 0) {
                size_t r0 = (size_t)m*E + base8;
                size_t r1 = (size_t)(m+8)*E + base8;
                g_q[r0 + p0]     = f2tf(v0*0.125f);
                g_q[r0 + p0 + 2] = f2tf(v1*0.125f);
                g_q[r1 + p0]     = f2tf(v2*0.125f);
                g_q[r1 + p0 + 2] = f2tf(v3*0.125f);
            } else {
                float* fbase = dout + (seg == 1 ? OUT_K : OUT_V);
                int ba = m >> 9,      t0 = m & 511;
                int bb = (m+8) >> 9,  t1 = (m+8) & 511;
                size_t ra = ((size_t)(ba*KVL) + CL + t0)*E;
                size_t rb = ((size_t)(bb*KVL) + CL + t1)*E;
                *(float2*)&fbase[ra + nl] = make_float2(v0, v1);
                *(float2*)&fbase[rb + nl] = make_float2(v2, v3);
                if (seg == 1) {
                    g_kt[ra + base8 + p0]     = f2tf(v0);
                    g_kt[ra + base8 + p0 + 2] = f2tf(v1);
                    g_kt[rb + base8 + p0]     = f2tf(v2);
                    g_kt[rb + base8 + p0 + 2] = f2tf(v3);
                } else {
                    uint2 u0; u0.x = f2tf(v0); u0.y = f2tf(v1);
                    uint2 u1; u1.x = f2tf(v2); u1.y = f2tf(v3);
                    *(uint2*)&g_vt[ra + nl] = u0;
                    *(uint2*)&g_vt[rb + nl] = u1;
                }
            }
        }
    }
}

// ---------------- output projection ------------------------------------------
__global__ __launch_bounds__(256)
void gemm_out(const float* __restrict__ bo, float* __restrict__ dout)
{
    int bn = blockIdx.x*128, bm = blockIdx.y*64;

    float acc[2][4][4];
    gemm_core(g_ctx, g_wot, bm, bn, acc);

    int tid = threadIdx.x;
    int warp = tid >> 5, lane = tid & 31, g = lane >> 2, tig = lane & 3;
    int wm = (warp >> 2)*32, wn = (warp & 3)*32;

    #pragma unroll
    for (int mt = 0; mt < 2; mt++) {
        int m = bm + wm + mt*16 + g;
        #pragma unroll
        for (int nt = 0; nt < 4; nt++) {
            int n = bn + wn + nt*8 + 2*tig;
            float b0 = bo[n], b1 = bo[n+1];
            *(float2*)&dout[(size_t)m*E + n] =
                make_float2(acc[mt][nt][0] + b0, acc[mt][nt][1] + b1);
            *(float2*)&dout[(size_t)(m+8)*E + n] =
                make_float2(acc[mt][nt][2] + b0, acc[mt][nt][3] + b1);
        }
    }
}

// ---------------- flash attention: split-KV, Q in SMEM, LDS.64 S-path --------
#define SWKN(r,o) ((o) ^ ((((unsigned)(r))&3u)<<3))
#define SWV(r,d)  ((d) ^ ((((unsigned)(r))&3u)<<3))

__global__ __launch_bounds__(128, 4)
void attn(const float* __restrict__ amask)
{
    __shared__ __align__(16) unsigned sQ[64*64];
    __shared__ __align__(16) unsigned sK[64*64];
    __shared__ __align__(16) unsigned sV[64*64];

    int qt    = blockIdx.x >> 1;
    int chunk = blockIdx.x & 1;
    int h = blockIdx.y, b = blockIdx.z;

    int tid  = threadIdx.x;
    int warp = tid >> 5, lane = tid & 31, g = lane >> 2, tig = lane & 3;
    int m0 = warp*16;

    int nkt  = 25 + qt;
    int half = nkt >> 1;
    int t0   = chunk ? half : 0;
    int ntiles = chunk ? (nkt - half) : half;

    unsigned qAddr = (unsigned)__cvta_generic_to_shared(sQ);
    unsigned kAddr = (unsigned)__cvta_generic_to_shared(sK);
    unsigned vAddr = (unsigned)__cvta_generic_to_shared(sV);

    const unsigned* kg = g_kt + ((size_t)b*KVL)*E + h*HD;
    const unsigned* vg = g_vt + ((size_t)b*KVL)*E + h*HD;

    auto issueK = [&](int tile) {
        const unsigned* src = kg + (size_t)tile*64*E;
        #pragma unroll
        for (int i = 0; i < 8; i++) {
            int c = tid + i*128;
            int row = c >> 4, c4 = (c & 15)*4;
            CP16(kAddr + (unsigned)((row*64 + SWKN(row, c4))*4),
                 src + (size_t)row*E + c4);
        }
    };
    auto issueV = [&](int tile) {
        const unsigned* src = vg + (size_t)tile*64*E;
        #pragma unroll
        for (int i = 0; i < 8; i++) {
            int c = tid + i*128;
            int row = c >> 4, c4 = (c & 15)*4;
            CP16(vAddr + (unsigned)((row*64 + SWV(row, c4))*4),
                 src + (size_t)row*E + c4);
        }
    };

    // prologue: Q tile + first K,V — one commit group
    {
        const unsigned* src = g_q + ((size_t)(b*QL + qt*64))*E + h*HD;
        #pragma unroll
        for (int i = 0; i < 8; i++) {
            int c = tid + i*128;
            int row = c >> 4, c4 = (c & 15)*4;
            CP16(qAddr + (unsigned)((row*64 + SWKN(row, c4))*4),
                 src + (size_t)row*E + c4);
        }
    }
    issueK(t0);
    issueV(t0);
    CPCOMMIT();

    float O[8][4];
    #pragma unroll
    for (int nt = 0; nt < 8; nt++)
        #pragma unroll
        for (int i = 0; i < 4; i++) O[nt][i] = 0.f;
    float mi0 = -1e30f, mi1 = -1e30f, li0 = 0.f, li1 = 0.f;

    for (int it = 0; it < ntiles; it++) {
        int kt = t0 + it;
        CPWAIT(0);
        __syncthreads();

        // ---- S = (Q/8) K^T  (LDS.64 paired fragments from permuted sQ/sK) ----
        float s[8][4];
        #pragma unroll
        for (int nt = 0; nt < 8; nt++)
            #pragma unroll
            for (int i = 0; i < 4; i++) s[nt][i] = 0.f;
        #pragma unroll
        for (int kc = 0; kc < 8; kc++) {
            int kb = kc*8 + 2*tig;
            uint2 aLo = *(const uint2*)&sQ[(m0+g  )*64 + SWKN(m0+g,   kb)];
            uint2 aHi = *(const uint2*)&sQ[(m0+g+8)*64 + SWKN(m0+g+8, kb)];
            #pragma unroll
            for (int nt = 0; nt < 8; nt++) {
                int col = nt*8 + g;
                uint2 bp = *(const uint2*)&sK[col*64 + SWKN(col, kb)];
                mma8(s[nt], aLo.x, aHi.x, aLo.y, aHi.y, bp.x, bp.y);
            }
        }

        __syncthreads();                         // sK fully consumed
        if (it + 1 < ntiles) issueK(kt+1);

        // ---- mask + online softmax ----
        int c0 = kt*64;
        const float* am = amask + (size_t)b*(CL+QL) + c0;
        bool causal = (chunk == 1) && (it == ntiles-1);
        #pragma unroll
        for (int nt = 0; nt < 8; nt++) {
            int j0 = nt*8 + 2*tig, j1 = j0 + 1;
            float a0 = __ldg(am + j0), a1 = __ldg(am + j1);
            s[nt][0] += a0; s[nt][1] += a1; s[nt][2] += a0; s[nt][3] += a1;
            if (causal) {
                int r0 = CL + qt*64 + m0 + g, r1 = r0 + 8;
                int cj0 = c0 + j0, cj1 = c0 + j1;
                if (cj0 > r0) s[nt][0] = -1e30f;
                if (cj1 > r0) s[nt][1] = -1e30f;
                if (cj0 > r1) s[nt][2] = -1e30f;
                if (cj1 > r1) s[nt][3] = -1e30f;
            }
        }

        float mx0 = -1e30f, mx1 = -1e30f;
        #pragma unroll
        for (int nt = 0; nt < 8; nt++) {
            mx0 = fmaxf(mx0, fmaxf(s[nt][0], s[nt][1]));
            mx1 = fmaxf(mx1, fmaxf(s[nt][2], s[nt][3]));
        }
        mx0 = fmaxf(mx0, __shfl_xor_sync(0xffffffffu, mx0, 1));
        mx0 = fmaxf(mx0, __shfl_xor_sync(0xffffffffu, mx0, 2));
        mx1 = fmaxf(mx1, __shfl_xor_sync(0xffffffffu, mx1, 1));
        mx1 = fmaxf(mx1, __shfl_xor_sync(0xffffffffu, mx1, 2));

        float mn0 = fmaxf(mi0, mx0), mn1 = fmaxf(mi1, mx1);
        float cor0 = __expf(mi0 - mn0), cor1 = __expf(mi1 - mn1);
        mi0 = mn0; mi1 = mn1;

        float sum0 = 0.f, sum1 = 0.f;
        #pragma unroll
        for (int nt = 0; nt < 8; nt++) {
            s[nt][0] = __expf(s[nt][0] - mn0); sum0 += s[nt][0];
            s[nt][1] = __expf(s[nt][1] - mn0); sum0 += s[nt][1];
            s[nt][2] = __expf(s[nt][2] - mn1); sum1 += s[nt][2];
            s[nt][3] = __expf(s[nt][3] - mn1); sum1 += s[nt][3];
        }
        sum0 += __shfl_xor_sync(0xffffffffu, sum0, 1);
        sum0 += __shfl_xor_sync(0xffffffffu, sum0, 2);
        sum1 += __shfl_xor_sync(0xffffffffu, sum1, 1);
        sum1 += __shfl_xor_sync(0xffffffffu, sum1, 2);
        li0 = li0*cor0 + sum0;
        li1 = li1*cor1 + sum1;
        #pragma unroll
        for (int nt = 0; nt < 8; nt++) {
            O[nt][0] *= cor0; O[nt][1] *= cor0;
            O[nt][2] *= cor1; O[nt][3] *= cor1;
        }

        // ---- O += P V  (P via cvt + shfl permutation) ----
        int l1 = (lane & 28) + (tig >> 1);
        int l2 = l1 + 2;
        bool odd = (tig & 1);
        #pragma unroll
        for (int kc = 0; kc < 8; kc++) {
            unsigned u0 = f2tf(s[kc][0]), u1 = f2tf(s[kc][1]);
            unsigned u2 = f2tf(s[kc][2]), u3 = f2tf(s[kc][3]);
            unsigned s00 = __shfl_sync(0xffffffffu, u0, l1);
            unsigned s01 = __shfl_sync(0xffffffffu, u1, l1);
            unsigned s02 = __shfl_sync(0xffffffffu, u2, l1);
            unsigned s03 = __shfl_sync(0xffffffffu, u3, l1);
            unsigned s10 = __shfl_sync(0xffffffffu, u0, l2);
            unsigned s11 = __shfl_sync(0xffffffffu, u1, l2);
            unsigned s12 = __shfl_sync(0xffffffffu, u2, l2);
            unsigned s13 = __shfl_sync(0xffffffffu, u3, l2);
            unsigned a0 = odd ? s01 : s00;
            unsigned a1 = odd ? s03 : s02;
            unsigned a2 = odd ? s11 : s10;
            unsigned a3 = odd ? s13 : s12;
            int kb = kc*8;
            #pragma unroll
            for (int nt = 0; nt < 8; nt++) {
                int dcol = nt*8 + g;
                unsigned b0 = sV[(kb+tig  )*64 + SWV(kb+tig,   dcol)];
                unsigned b1 = sV[(kb+tig+4)*64 + SWV(kb+tig+4, dcol)];
                mma8(O[nt], a0, a1, a2, a3, b0, b1);
            }
        }

        __syncthreads();                          // sV fully consumed
        if (it + 1 < ntiles) issueV(kt+1);
        CPCOMMIT();                               // group = K(t+1)+V(t+1)
    }

    // ---- write partials (unnormalized O, m, l) ----
    size_t rowbase = ((size_t)(b*NH + h))*QL + qt*64;
    float* po = g_po + ((size_t)chunk*PO_ROWS + rowbase)*HD;
    #pragma unroll
    for (int nt = 0; nt < 8; nt++) {
        int col = nt*8 + 2*tig;
        *(float2*)&po[(size_t)(m0+g)*HD + col]   = make_float2(O[nt][0], O[nt][1]);
        *(float2*)&po[(size_t)(m0+g+8)*HD + col] = make_float2(O[nt][2], O[nt][3]);
    }
    if (tig == 0) {
        size_t mb = (size_t)chunk*PO_ROWS + rowbase;
        g_pm[mb + m0 + g]     = mi0;
        g_pl[mb + m0 + g]     = li0;
        g_pm[mb + m0 + g + 8] = mi1;
        g_pl[mb + m0 + g + 8] = li1;
    }
}

// ---------------- combine split-KV partials -> ctx (tf32, PERMUTED) ----------
__global__ void combine_attn()
{
    int idx = blockIdx.x*256 + threadIdx.x;      // 0 .. 524287
    int d4  = idx & 15;
    int row = idx >> 4;                          // 0 .. 32767

    float m0 = g_pm[row], m1 = g_pm[PO_ROWS + row];
    float l0 = g_pl[row], l1 = g_pl[PO_ROWS + row];
    float m  = fmaxf(m0, m1);
    float w0 = __expf(m0 - m), w1 = __expf(m1 - m);
    float inv = 1.f / (w0*l0 + w1*l1);
    w0 *= inv; w1 *= inv;

    float4 o0 = ((const float4*)g_po)[(size_t)row*16 + d4];
    float4 o1 = ((const float4*)g_po)[(size_t)(PO_ROWS + row)*16 + d4];

    int q = row & 511, h = (row >> 9) & 15, b = row >> 13;
    size_t base = (size_t)(b*QL + q)*E + h*HD + d4*4;
    size_t G    = base & ~(size_t)7;
    int   off   = (base & 4) ? 1 : 0;
    g_ctx[G + off + 0] = f2tf(w0*o0.x + w1*o1.x);
    g_ctx[G + off + 2] = f2tf(w0*o0.y + w1*o1.y);
    g_ctx[G + off + 4] = f2tf(w0*o0.z + w1*o1.z);
    g_ctx[G + off + 6] = f2tf(w0*o0.w + w1*o1.w);
}

// ---------------- launch ----------------------------------------------------
extern "C" void kernel_launch(void* const* d_in, const int* in_sizes, int n_in,
                              void* d_out, int out_size)
{
    const float* X     = (const float*)d_in[0];
    const float* amask = (const float*)d_in[1];
    const float* kc    = (const float*)d_in[2];
    const float* vc    = (const float*)d_in[3];
    const float* Wq    = (const float*)d_in[4];
    const float* bq    = (const float*)d_in[5];
    const float* Wk    = (const float*)d_in[6];
    const float* bk    = (const float*)d_in[7];
    const float* Wv    = (const float*)d_in[8];
    const float* bv    = (const float*)d_in[9];
    const float* Wo    = (const float*)d_in[10];
    const float* bo    = (const float*)d_in[11];
    float* out = (float*)d_out;

    convert_tf32<<<6144, 256>>>((const float4*)X, (const float4*)Wq,
                                (const float4*)Wk, (const float4*)Wv,
                                (const float4*)Wo);
    {
        int total = BZ*CL*E/4;
        copy_cache<<<(total + 255)/256, 256>>>((const float4*)kc,
                                               (const float4*)vc, out);
    }
    {
        dim3 grid(3*E/128, MROWS/64);        // 24 x 32 = 768 blocks
        gemm_qkv<<<grid, 256>>>(bq, bk, bv, out);
    }
    {
        dim3 grid(16, NH, BZ);               // (qt,chunk) x 16 x 4 = 1024 blocks
        attn<<<grid, 128>>>(amask);
    }
    combine_attn<<<2048, 256>>>();
    {
        dim3 grid(E/128, MROWS/64);          // 8 x 32 = 256 blocks
        gemm_out<<<grid, 256>>>(bo, out);
    }
}

// round 17
// speedup vs baseline: 1.1936x; 1.0939x over previous
#include <cuda_runtime.h>
#include <math.h>

#define BZ   4
#define QL   512
#define CL   1536
#define KVL  2048
#define E    1024
#define NH   16
#define HD   64
#define MROWS (BZ*QL)   // 2048

#define OUT_K ((size_t)MROWS*E)                       // 2097152
#define OUT_V (OUT_K + (size_t)BZ*KVL*E)              // 10485760

#define PO_ROWS (BZ*NH*QL)    // 32768

// ---------------- scratch -----------------------------------------------------
// tf32 (u32) operands use the k-pair permuted layout within each 8-group:
//   perm8(t) = t<4 ? 2t : 2(t-4)+1.
// g_vp: V as fp16 position-pairs: u32 at [b][r][d] = {lo=V[2r][d], hi=V[2r+1][d]}.
__device__ unsigned g_xt [MROWS*E];       // X  tf32, PERMUTED
__device__ unsigned g_wqt[E*E];           // Wq tf32 [n][k], PERMUTED
__device__ unsigned g_wkt[E*E];           // PERMUTED
__device__ unsigned g_wvt[E*E];           // PERMUTED
__device__ unsigned g_wot[E*E];           // PERMUTED
__device__ unsigned g_q  [MROWS*E];       // Q proj, tf32, 1/8-scaled, PERMUTED
__device__ unsigned g_ctx[MROWS*E];       // attention ctx, tf32, PERMUTED
__device__ unsigned g_kt [(size_t)BZ*KVL*E];    // full K tf32, PERMUTED
__device__ unsigned g_vp [(size_t)BZ*(KVL/2)*E];// full V fp16 pos-pairs

// split-KV partials
__device__ float g_po[(size_t)2*PO_ROWS*HD];
__device__ float g_pm[2*PO_ROWS];
__device__ float g_pl[2*PO_ROWS];

// ---------------- helpers ----------------------------------------------------
__device__ __forceinline__ unsigned f2tf(float f) {
    unsigned u;
    asm("cvt.rna.tf32.f32 %0, %1;" : "=r"(u) : "f"(f));
    return u;
}
__device__ __forceinline__ unsigned f2h2(float lo, float hi) {
    unsigned d;
    asm("cvt.rn.f16x2.f32 %0, %1, %2;" : "=r"(d) : "f"(hi), "f"(lo));
    return d;
}

__device__ __forceinline__ void mma8(float* c,
                                     unsigned a0, unsigned a1, unsigned a2, unsigned a3,
                                     unsigned b0, unsigned b1)
{
    asm volatile(
        "mma.sync.aligned.m16n8k8.row.col.f32.tf32.tf32.f32 "
        "{%0,%1,%2,%3}, {%4,%5,%6,%7}, {%8,%9}, {%0,%1,%2,%3};\n"
        : "+f"(c[0]), "+f"(c[1]), "+f"(c[2]), "+f"(c[3])
        : "r"(a0), "r"(a1), "r"(a2), "r"(a3), "r"(b0), "r"(b1));
}

__device__ __forceinline__ void mma16h(float* c,
                                       unsigned a0, unsigned a1, unsigned a2, unsigned a3,
                                       unsigned b0, unsigned b1)
{
    asm volatile(
        "mma.sync.aligned.m16n8k16.row.col.f32.f16.f16.f32 "
        "{%0,%1,%2,%3}, {%4,%5,%6,%7}, {%8,%9}, {%0,%1,%2,%3};\n"
        : "+f"(c[0]), "+f"(c[1]), "+f"(c[2]), "+f"(c[3])
        : "r"(a0), "r"(a1), "r"(a2), "r"(a3), "r"(b0), "r"(b1));
}

#define CP16(dst, src) \
    asm volatile("cp.async.cg.shared.global [%0], [%1], 16;\n" \
                 :: "r"(dst), "l"(src))
#define CPCOMMIT() asm volatile("cp.async.commit_group;\n" ::: "memory")
#define CPWAIT(n)  asm volatile("cp.async.wait_group %0;\n" :: "n"(n) : "memory")

// ---------------- convert inputs to tf32 (k-pair permuted) -------------------
__global__ void convert_tf32(const float4* __restrict__ X,
                             const float4* __restrict__ Wq,
                             const float4* __restrict__ Wk,
                             const float4* __restrict__ Wv,
                             const float4* __restrict__ Wo)
{
    int i = blockIdx.x*256 + threadIdx.x;
    const float4* src; unsigned* dst; int off4;
    if (i < 524288)       { src = X;  dst = g_xt;  off4 = i; }
    else if (i < 786432)  { src = Wq; dst = g_wqt; off4 = i - 524288; }
    else if (i < 1048576) { src = Wk; dst = g_wkt; off4 = i - 786432; }
    else if (i < 1310720) { src = Wv; dst = g_wvt; off4 = i - 1048576; }
    else                  { src = Wo; dst = g_wot; off4 = i - 1310720; }
    float4 v = src[off4];
    size_t eb = (size_t)off4*4;
    size_t G  = eb & ~(size_t)7;
    int   off = (eb & 4) ? 1 : 0;
    dst[G + off + 0] = f2tf(v.x);
    dst[G + off + 2] = f2tf(v.y);
    dst[G + off + 4] = f2tf(v.z);
    dst[G + off + 6] = f2tf(v.w);
}

// ---------------- cache copy: pos-pair based ---------------------------------
// Thread = (b, pair r in [0,CL/2), d4). Writes f32 K/V to dout (both positions),
// permuted tf32 K, and fp16 pos-paired V (one uint4).
__global__ void copy_cache(const float4* __restrict__ kc,
                           const float4* __restrict__ vc,
                           float* __restrict__ dout)
{
    const int per_b = (CL/2)*(E/4);            // 768*256 = 196608
    int idx = blockIdx.x*blockDim.x + threadIdx.x;
    if (idx >= BZ*per_b) return;
    int b = idx / per_b, rem = idx - b*per_b;
    int r  = rem >> 8;                         // pair 0..767
    int d4 = rem & 255;

    size_t s0 = ((size_t)b*CL + 2*r)*256 + d4;     // float4 idx in cache
    size_t s1 = s0 + 256;
    float4 k0 = kc[s0], k1 = kc[s1];
    float4 v0 = vc[s0], v1 = vc[s1];

    size_t d0 = ((size_t)b*KVL + 2*r)*256 + d4;    // float4 idx in dout
    size_t d1 = d0 + 256;
    ((float4*)(dout + OUT_K))[d0] = k0;
    ((float4*)(dout + OUT_K))[d1] = k1;
    ((float4*)(dout + OUT_V))[d0] = v0;
    ((float4*)(dout + OUT_V))[d1] = v1;

    // K -> permuted tf32 (per position)
    {
        size_t eb = d0*4, G = eb & ~(size_t)7;
        int off = (eb & 4) ? 1 : 0;
        g_kt[G + off + 0] = f2tf(k0.x);
        g_kt[G + off + 2] = f2tf(k0.y);
        g_kt[G + off + 4] = f2tf(k0.z);
        g_kt[G + off + 6] = f2tf(k0.w);
        eb = d1*4; G = eb & ~(size_t)7;
        off = (eb & 4) ? 1 : 0;
        g_kt[G + off + 0] = f2tf(k1.x);
        g_kt[G + off + 2] = f2tf(k1.y);
        g_kt[G + off + 4] = f2tf(k1.z);
        g_kt[G + off + 6] = f2tf(k1.w);
    }

    // V -> fp16 pos-pairs
    uint4 u;
    u.x = f2h2(v0.x, v1.x);
    u.y = f2h2(v0.y, v1.y);
    u.z = f2h2(v0.z, v1.z);
    u.w = f2h2(v0.w, v1.w);
    ((uint4*)g_vp)[((size_t)b*1024 + r)*256 + d4] = u;
}

// ---------------- tf32 GEMM core (cp.async, 2-stage, BK=32, LDS.64) ----------
#define GST 40
#define GSTAGE (192*GST)

__device__ __forceinline__
void gemm_core(const unsigned* __restrict__ AGLOB,
               const unsigned* __restrict__ BGLOB,
               int bm, int nrow0, float acc[2][4][4])
{
    __shared__ __align__(16) unsigned sAB[2*GSTAGE];
    unsigned* Asm[2] = { sAB,          sAB + GSTAGE };
    unsigned* Bsm[2] = { sAB + 64*GST, sAB + GSTAGE + 64*GST };
    unsigned aAddr[2], bAddr[2];
    aAddr[0] = (unsigned)__cvta_generic_to_shared(Asm[0]);
    aAddr[1] = (unsigned)__cvta_generic_to_shared(Asm[1]);
    bAddr[0] = (unsigned)__cvta_generic_to_shared(Bsm[0]);
    bAddr[1] = (unsigned)__cvta_generic_to_shared(Bsm[1]);

    int tid = threadIdx.x;
    int warp = tid >> 5, lane = tid & 31, g = lane >> 2, tig = lane & 3;
    int wm = (warp >> 2)*32, wn = (warp & 3)*32;
    int rc  = tid >> 3;
    int cc  = (tid & 7)*4;

    auto issue = [&](int st, int k0) {
        CP16(aAddr[st] + (unsigned)((rc*GST + cc)*4),
             AGLOB + (size_t)(bm + rc)*E + k0 + cc);
        CP16(aAddr[st] + (unsigned)(((rc+32)*GST + cc)*4),
             AGLOB + (size_t)(bm + rc + 32)*E + k0 + cc);
        #pragma unroll
        for (int br = 0; br < 4; br++)
            CP16(bAddr[st] + (unsigned)(((rc + br*32)*GST + cc)*4),
                 BGLOB + (size_t)(nrow0 + rc + br*32)*E + k0 + cc);
    };

    #pragma unroll
    for (int mt = 0; mt < 2; mt++)
        #pragma unroll
        for (int nt = 0; nt < 4; nt++)
            #pragma unroll
            for (int i = 0; i < 4; i++) acc[mt][nt][i] = 0.f;

    issue(0, 0);  CPCOMMIT();
    issue(1, 32); CPCOMMIT();

    for (int kt = 0; kt < 32; kt++) {
        int cur = kt & 1;
        if (kt < 31) { CPWAIT(1); } else { CPWAIT(0); }
        __syncthreads();
        #pragma unroll
        for (int kh = 0; kh < 4; kh++) {
            int kb = kh*8 + 2*tig;
            uint2 af[2][2];
            #pragma unroll
            for (int mt = 0; mt < 2; mt++) {
                int r = wm + mt*16;
                af[mt][0] = *(const uint2*)&Asm[cur][(r+g  )*GST + kb];
                af[mt][1] = *(const uint2*)&Asm[cur][(r+g+8)*GST + kb];
            }
            uint2 bf[4];
            #pragma unroll
            for (int nt = 0; nt < 4; nt++) {
                int cidx = wn + nt*8 + g;
                bf[nt] = *(const uint2*)&Bsm[cur][cidx*GST + kb];
            }
            #pragma unroll
            for (int mt = 0; mt < 2; mt++)
                #pragma unroll
                for (int nt = 0; nt < 4; nt++)
                    mma8(acc[mt][nt], af[mt][0].x, af[mt][1].x,
                         af[mt][0].y, af[mt][1].y, bf[nt].x, bf[nt].y);
        }
        __syncthreads();
        if (kt + 2 < 32) { issue(cur, (kt+2)*32); CPCOMMIT(); }
    }
}

// ---------------- QKV projection ---------------------------------------------
__global__ __launch_bounds__(256)
void gemm_qkv(const float* __restrict__ bq, const float* __restrict__ bk,
              const float* __restrict__ bv, float* __restrict__ dout)
{
    int bn = blockIdx.x*128, bm = blockIdx.y*64;
    int seg = bn >> 10;            // 0=Q 1=K 2=V
    int nrow0 = bn & (E-1);
    const unsigned* Bglob = (seg == 0) ? g_wqt : (seg == 1) ? g_wkt : g_wvt;
    const float*    bias  = (seg == 0) ? bq   : (seg == 1) ? bk    : bv;

    float acc[2][4][4];
    gemm_core(g_xt, Bglob, bm, nrow0, acc);

    int tid = threadIdx.x;
    int warp = tid >> 5, lane = tid & 31, g = lane >> 2, tig = lane & 3;
    int wm = (warp >> 2)*32, wn = (warp & 3)*32;

    int p0 = (tig < 2) ? (4*tig) : (4*(tig-2) + 1);

    #pragma unroll
    for (int mt = 0; mt < 2; mt++) {
        int m = bm + wm + mt*16 + g;
        #pragma unroll
        for (int nt = 0; nt < 4; nt++) {
            int nl = nrow0 + wn + nt*8 + 2*tig;
            float b0 = bias[nl], b1 = bias[nl+1];
            float v0 = acc[mt][nt][0] + b0, v1 = acc[mt][nt][1] + b1;
            float v2 = acc[mt][nt][2] + b0, v3 = acc[mt][nt][3] + b1;
            int base8 = nl & ~7;
            if (seg == 0) {
                size_t r0 = (size_t)m*E + base8;
                size_t r1 = (size_t)(m+8)*E + base8;
                g_q[r0 + p0]     = f2tf(v0*0.125f);
                g_q[r0 + p0 + 2] = f2tf(v1*0.125f);
                g_q[r1 + p0]     = f2tf(v2*0.125f);
                g_q[r1 + p0 + 2] = f2tf(v3*0.125f);
            } else if (seg == 1) {
                float* fbase = dout + OUT_K;
                int ba = m >> 9,      t0 = m & 511;
                int bb = (m+8) >> 9,  t1 = (m+8) & 511;
                size_t ra = ((size_t)(ba*KVL) + CL + t0)*E;
                size_t rb = ((size_t)(bb*KVL) + CL + t1)*E;
                *(float2*)&fbase[ra + nl] = make_float2(v0, v1);
                *(float2*)&fbase[rb + nl] = make_float2(v2, v3);
                g_kt[ra + base8 + p0]     = f2tf(v0);
                g_kt[ra + base8 + p0 + 2] = f2tf(v1);
                g_kt[rb + base8 + p0]     = f2tf(v2);
                g_kt[rb + base8 + p0 + 2] = f2tf(v3);
            } else {
                float* fbase = dout + OUT_V;
                int ba = m >> 9,      t0 = m & 511;
                int bb = (m+8) >> 9,  t1 = (m+8) & 511;
                size_t ra = ((size_t)(ba*KVL) + CL + t0)*E;
                size_t rb = ((size_t)(bb*KVL) + CL + t1)*E;
                *(float2*)&fbase[ra + nl] = make_float2(v0, v1);
                *(float2*)&fbase[rb + nl] = make_float2(v2, v3);
                // fp16 pos-pairs: partner lane g+1 holds pos m+1 (same cols)
                float p0f = __shfl_down_sync(0xffffffffu, v0, 4);
                float p1f = __shfl_down_sync(0xffffffffu, v1, 4);
                float p2f = __shfl_down_sync(0xffffffffu, v2, 4);
                float p3f = __shfl_down_sync(0xffffffffu, v3, 4);
                if ((g & 1) == 0) {
                    int rpa = (CL + t0) >> 1;       // pos pair of row m
                    int rpb = (CL + t1) >> 1;       // pos pair of row m+8
                    uint2 ua; ua.x = f2h2(v0, p0f); ua.y = f2h2(v1, p1f);
                    uint2 ub; ub.x = f2h2(v2, p2f); ub.y = f2h2(v3, p3f);
                    *(uint2*)&g_vp[((size_t)(ba*1024) + rpa)*E + nl] = ua;
                    *(uint2*)&g_vp[((size_t)(bb*1024) + rpb)*E + nl] = ub;
                }
            }
        }
    }
}

// ---------------- output projection ------------------------------------------
__global__ __launch_bounds__(256)
void gemm_out(const float* __restrict__ bo, float* __restrict__ dout)
{
    int bn = blockIdx.x*128, bm = blockIdx.y*64;

    float acc[2][4][4];
    gemm_core(g_ctx, g_wot, bm, bn, acc);

    int tid = threadIdx.x;
    int warp = tid >> 5, lane = tid & 31, g = lane >> 2, tig = lane & 3;
    int wm = (warp >> 2)*32, wn = (warp & 3)*32;

    #pragma unroll
    for (int mt = 0; mt < 2; mt++) {
        int m = bm + wm + mt*16 + g;
        #pragma unroll
        for (int nt = 0; nt < 4; nt++) {
            int n = bn + wn + nt*8 + 2*tig;
            float b0 = bo[n], b1 = bo[n+1];
            *(float2*)&dout[(size_t)m*E + n] =
                make_float2(acc[mt][nt][0] + b0, acc[mt][nt][1] + b1);
            *(float2*)&dout[(size_t)(m+8)*E + n] =
                make_float2(acc[mt][nt][2] + b0, acc[mt][nt][3] + b1);
        }
    }
}

// ---------------- flash attention: tf32 S + fp16 PV (zero-shuffle P) ---------
#define SWKN(r,o) ((o) ^ ((((unsigned)(r))&3u)<<3))

__global__ __launch_bounds__(128, 4)
void attn(const float* __restrict__ amask)
{
    __shared__ __align__(16) unsigned sQ[64*64];
    __shared__ __align__(16) unsigned sK[64*64];
    __shared__ __align__(16) unsigned sVp[32*64];   // fp16 pos-pairs, swizzled

    int qt    = blockIdx.x >> 1;
    int chunk = blockIdx.x & 1;
    int h = blockIdx.y, b = blockIdx.z;

    int tid  = threadIdx.x;
    int warp = tid >> 5, lane = tid & 31, g = lane >> 2, tig = lane & 3;
    int m0 = warp*16;

    int nkt  = 25 + qt;
    int half = nkt >> 1;
    int t0   = chunk ? half : 0;
    int ntiles = chunk ? (nkt - half) : half;

    unsigned qAddr = (unsigned)__cvta_generic_to_shared(sQ);
    unsigned kAddr = (unsigned)__cvta_generic_to_shared(sK);
    unsigned vAddr = (unsigned)__cvta_generic_to_shared(sVp);

    const unsigned* kg = g_kt + ((size_t)b*KVL)*E + h*HD;
    const unsigned* vg = g_vp + ((size_t)b*1024)*E + h*HD;

    auto issueK = [&](int tile) {
        const unsigned* src = kg + (size_t)tile*64*E;
        #pragma unroll
        for (int i = 0; i < 8; i++) {
            int c = tid + i*128;
            int row = c >> 4, c4 = (c & 15)*4;
            CP16(kAddr + (unsigned)((row*64 + SWKN(row, c4))*4),
                 src + (size_t)row*E + c4);
        }
    };
    auto issueV = [&](int tile) {
        const unsigned* src = vg + (size_t)tile*32*E;
        #pragma unroll
        for (int i = 0; i < 4; i++) {
            int c = tid + i*128;
            int row = c >> 4, c4 = (c & 15)*4;   // row 0..31, c4 0..60
            CP16(vAddr + (unsigned)((row*64 + (c4 ^ ((row&7)<<3)))*4),
                 src + (size_t)row*E + c4);
        }
    };

    // prologue: Q tile + first K,V — one commit group
    {
        const unsigned* src = g_q + ((size_t)(b*QL + qt*64))*E + h*HD;
        #pragma unroll
        for (int i = 0; i < 8; i++) {
            int c = tid + i*128;
            int row = c >> 4, c4 = (c & 15)*4;
            CP16(qAddr + (unsigned)((row*64 + SWKN(row, c4))*4),
                 src + (size_t)row*E + c4);
        }
    }
    issueK(t0);
    issueV(t0);
    CPCOMMIT();

    float O[8][4];
    #pragma unroll
    for (int nt = 0; nt < 8; nt++)
        #pragma unroll
        for (int i = 0; i < 4; i++) O[nt][i] = 0.f;
    float mi0 = -1e30f, mi1 = -1e30f, li0 = 0.f, li1 = 0.f;

    for (int it = 0; it < ntiles; it++) {
        int kt = t0 + it;
        CPWAIT(0);
        __syncthreads();

        // ---- S = (Q/8) K^T  (tf32, LDS.64 paired fragments) ----
        float s[8][4];
        #pragma unroll
        for (int nt = 0; nt < 8; nt++)
            #pragma unroll
            for (int i = 0; i < 4; i++) s[nt][i] = 0.f;
        #pragma unroll
        for (int kc = 0; kc < 8; kc++) {
            int kb = kc*8 + 2*tig;
            uint2 aLo = *(const uint2*)&sQ[(m0+g  )*64 + SWKN(m0+g,   kb)];
            uint2 aHi = *(const uint2*)&sQ[(m0+g+8)*64 + SWKN(m0+g+8, kb)];
            #pragma unroll
            for (int nt = 0; nt < 8; nt++) {
                int col = nt*8 + g;
                uint2 bp = *(const uint2*)&sK[col*64 + SWKN(col, kb)];
                mma8(s[nt], aLo.x, aHi.x, aLo.y, aHi.y, bp.x, bp.y);
            }
        }

        __syncthreads();                         // sK fully consumed
        if (it + 1 < ntiles) issueK(kt+1);

        // ---- mask + online softmax ----
        int c0 = kt*64;
        const float* am = amask + (size_t)b*(CL+QL) + c0;
        bool causal = (chunk == 1) && (it == ntiles-1);
        #pragma unroll
        for (int nt = 0; nt < 8; nt++) {
            int j0 = nt*8 + 2*tig, j1 = j0 + 1;
            float a0 = __ldg(am + j0), a1 = __ldg(am + j1);
            s[nt][0] += a0; s[nt][1] += a1; s[nt][2] += a0; s[nt][3] += a1;
            if (causal) {
                int r0 = CL + qt*64 + m0 + g, r1 = r0 + 8;
                int cj0 = c0 + j0, cj1 = c0 + j1;
                if (cj0 > r0) s[nt][0] = -1e30f;
                if (cj1 > r0) s[nt][1] = -1e30f;
                if (cj0 > r1) s[nt][2] = -1e30f;
                if (cj1 > r1) s[nt][3] = -1e30f;
            }
        }

        float mx0 = -1e30f, mx1 = -1e30f;
        #pragma unroll
        for (int nt = 0; nt < 8; nt++) {
            mx0 = fmaxf(mx0, fmaxf(s[nt][0], s[nt][1]));
            mx1 = fmaxf(mx1, fmaxf(s[nt][2], s[nt][3]));
        }
        mx0 = fmaxf(mx0, __shfl_xor_sync(0xffffffffu, mx0, 1));
        mx0 = fmaxf(mx0, __shfl_xor_sync(0xffffffffu, mx0, 2));
        mx1 = fmaxf(mx1, __shfl_xor_sync(0xffffffffu, mx1, 1));
        mx1 = fmaxf(mx1, __shfl_xor_sync(0xffffffffu, mx1, 2));

        float mn0 = fmaxf(mi0, mx0), mn1 = fmaxf(mi1, mx1);
        float cor0 = __expf(mi0 - mn0), cor1 = __expf(mi1 - mn1);
        mi0 = mn0; mi1 = mn1;

        float sum0 = 0.f, sum1 = 0.f;
        #pragma unroll
        for (int nt = 0; nt < 8; nt++) {
            s[nt][0] = __expf(s[nt][0] - mn0); sum0 += s[nt][0];
            s[nt][1] = __expf(s[nt][1] - mn0); sum0 += s[nt][1];
            s[nt][2] = __expf(s[nt][2] - mn1); sum1 += s[nt][2];
            s[nt][3] = __expf(s[nt][3] - mn1); sum1 += s[nt][3];
        }
        sum0 += __shfl_xor_sync(0xffffffffu, sum0, 1);
        sum0 += __shfl_xor_sync(0xffffffffu, sum0, 2);
        sum1 += __shfl_xor_sync(0xffffffffu, sum1, 1);
        sum1 += __shfl_xor_sync(0xffffffffu, sum1, 2);
        li0 = li0*cor0 + sum0;
        li1 = li1*cor1 + sum1;
        #pragma unroll
        for (int nt = 0; nt < 8; nt++) {
            O[nt][0] *= cor0; O[nt][1] *= cor0;
            O[nt][2] *= cor1; O[nt][3] *= cor1;
        }

        // ---- O += P V  (fp16 m16n8k16; P = own accumulator registers) ----
        #pragma unroll
        for (int kc = 0; kc < 4; kc++) {
            unsigned a0 = f2h2(s[2*kc  ][0], s[2*kc  ][1]);
            unsigned a1 = f2h2(s[2*kc  ][2], s[2*kc  ][3]);
            unsigned a2 = f2h2(s[2*kc+1][0], s[2*kc+1][1]);
            unsigned a3 = f2h2(s[2*kc+1][2], s[2*kc+1][3]);
            int r0 = kc*8 + tig, r1 = r0 + 4;
            #pragma unroll
            for (int nt = 0; nt < 8; nt++) {
                int dcol = nt*8 + g;
                unsigned b0 = sVp[r0*64 + (dcol ^ ((r0&7)<<3))];
                unsigned b1 = sVp[r1*64 + (dcol ^ ((r1&7)<<3))];
                mma16h(O[nt], a0, a1, a2, a3, b0, b1);
            }
        }

        __syncthreads();                          // sVp fully consumed
        if (it + 1 < ntiles) issueV(kt+1);
        CPCOMMIT();                               // group = K(t+1)+V(t+1)
    }

    // ---- write partials (unnormalized O, m, l) ----
    size_t rowbase = ((size_t)(b*NH + h))*QL + qt*64;
    float* po = g_po + ((size_t)chunk*PO_ROWS + rowbase)*HD;
    #pragma unroll
    for (int nt = 0; nt < 8; nt++) {
        int col = nt*8 + 2*tig;
        *(float2*)&po[(size_t)(m0+g)*HD + col]   = make_float2(O[nt][0], O[nt][1]);
        *(float2*)&po[(size_t)(m0+g+8)*HD + col] = make_float2(O[nt][2], O[nt][3]);
    }
    if (tig == 0) {
        size_t mb = (size_t)chunk*PO_ROWS + rowbase;
        g_pm[mb + m0 + g]     = mi0;
        g_pl[mb + m0 + g]     = li0;
        g_pm[mb + m0 + g + 8] = mi1;
        g_pl[mb + m0 + g + 8] = li1;
    }
}

// ---------------- combine split-KV partials -> ctx (tf32, PERMUTED) ----------
__global__ void combine_attn()
{
    int idx = blockIdx.x*256 + threadIdx.x;      // 0 .. 524287
    int d4  = idx & 15;
    int row = idx >> 4;                          // 0 .. 32767

    float m0 = g_pm[row], m1 = g_pm[PO_ROWS + row];
    float l0 = g_pl[row], l1 = g_pl[PO_ROWS + row];
    float m  = fmaxf(m0, m1);
    float w0 = __expf(m0 - m), w1 = __expf(m1 - m);
    float inv = 1.f / (w0*l0 + w1*l1);
    w0 *= inv; w1 *= inv;

    float4 o0 = ((const float4*)g_po)[(size_t)row*16 + d4];
    float4 o1 = ((const float4*)g_po)[(size_t)(PO_ROWS + row)*16 + d4];

    int q = row & 511, h = (row >> 9) & 15, b = row >> 13;
    size_t base = (size_t)(b*QL + q)*E + h*HD + d4*4;
    size_t G    = base & ~(size_t)7;
    int   off   = (base & 4) ? 1 : 0;
    g_ctx[G + off + 0] = f2tf(w0*o0.x + w1*o1.x);
    g_ctx[G + off + 2] = f2tf(w0*o0.y + w1*o1.y);
    g_ctx[G + off + 4] = f2tf(w0*o0.z + w1*o1.z);
    g_ctx[G + off + 6] = f2tf(w0*o0.w + w1*o1.w);
}

// ---------------- launch ----------------------------------------------------
extern "C" void kernel_launch(void* const* d_in, const int* in_sizes, int n_in,
                              void* d_out, int out_size)
{
    const float* X     = (const float*)d_in[0];
    const float* amask = (const float*)d_in[1];
    const float* kc    = (const float*)d_in[2];
    const float* vc    = (const float*)d_in[3];
    const float* Wq    = (const float*)d_in[4];
    const float* bq    = (const float*)d_in[5];
    const float* Wk    = (const float*)d_in[6];
    const float* bk    = (const float*)d_in[7];
    const float* Wv    = (const float*)d_in[8];
    const float* bv    = (const float*)d_in[9];
    const float* Wo    = (const float*)d_in[10];
    const float* bo    = (const float*)d_in[11];
    float* out = (float*)d_out;

    convert_tf32<<<6144, 256>>>((const float4*)X, (const float4*)Wq,
                                (const float4*)Wk, (const float4*)Wv,
                                (const float4*)Wo);
    {
        int total = BZ*(CL/2)*(E/4);             // 786432
        copy_cache<<<(total + 255)/256, 256>>>((const float4*)kc,
                                               (const float4*)vc, out);
    }
    {
        dim3 grid(3*E/128, MROWS/64);        // 24 x 32 = 768 blocks
        gemm_qkv<<<grid, 256>>>(bq, bk, bv, out);
    }
    {
        dim3 grid(16, NH, BZ);               // (qt,chunk) x 16 x 4 = 1024 blocks
        attn<<<grid, 128>>>(amask);
    }
    combine_attn<<<2048, 256>>>();
    {
        dim3 grid(E/128, MROWS/64);          // 8 x 32 = 256 blocks
        gemm_out<<<grid, 256>>>(bo, out);
    }
}